// round 3
// baseline (speedup 1.0000x reference)
#include <cuda_runtime.h>
#include <cstdint>

// Problem constants
#define BB 256
#define SS 2048
#define TT 64
#define PF 4

// Partial results: [0..255] = fwd per batch, [256..511] = -gold per batch
__device__ float g_partial[2 * BB];

// ---------------- dtype detection helpers ----------------
// mask: 0 = uint8 (bool), 1 = int32, 2 = float32
__device__ __forceinline__ int detect_mask_kind(const void* m) {
    unsigned u = *reinterpret_cast<const unsigned*>(m);
    if (u == 0x3f800000u) return 2;      // float 1.0
    if (u == 1u)          return 1;      // int32 1
    return 0;                             // bytes 01 01 01 01 (bool; L>=1024 so first 4 true)
}
__device__ __forceinline__ int mask_nz(const void* m, int kind, size_t i) {
    if (kind == 0) return reinterpret_cast<const unsigned char*>(m)[i] != 0;
    if (kind == 1) return reinterpret_cast<const int*>(m)[i] != 0;
    return reinterpret_cast<const float*>(m)[i] != 0.0f;
}
__device__ __forceinline__ bool detect_tags64(const void* t) {
    const int* p = reinterpret_cast<const int*>(t);
    bool all_hi_zero = true;
#pragma unroll
    for (int k = 0; k < 8; k++)
        if (p[2 * k + 1] != 0) all_hi_zero = false;
    return all_hi_zero;
}
__device__ __forceinline__ int tag_at(const void* t, bool is64, size_t i) {
    if (is64) return (int)reinterpret_cast<const long long*>(t)[i];
    return reinterpret_cast<const int*>(t)[i];
}

// ---------------- packed f32x2 helpers ----------------
__device__ __forceinline__ void fma2(unsigned long long& d,
                                     unsigned long long a, unsigned long long b) {
    asm("fma.rn.f32x2 %0, %1, %2, %0;" : "+l"(d) : "l"(a), "l"(b));
}
__device__ __forceinline__ unsigned long long add2(unsigned long long a,
                                                   unsigned long long b) {
    unsigned long long d;
    asm("add.rn.f32x2 %0, %1, %2;" : "=l"(d) : "l"(a), "l"(b));
    return d;
}

// ---------------- forward (log-partition) kernel ----------------
// One CTA (4 warps) per batch chain. Warp w owns states j in [16w, 16w+16);
// lanes l and l^16 duplicate j, splitting the i-sum into halves of 32.
// Linear-domain recurrence with lag-1 power-of-2 rescale (exact), ONE
// __syncthreads per step, double-buffered w.
__global__ void __launch_bounds__(128)
crf_fwd_kernel(const float* __restrict__ feats,
               const float* __restrict__ trans,
               const float* __restrict__ startt,
               const float* __restrict__ endt,
               const void* __restrict__ mask) {
    __shared__ __align__(16) float wbuf[2][TT];
    __shared__ float sscale[2];
    __shared__ int   swc[4];
    __shared__ int   sL;

    const int b   = blockIdx.x;
    const int tid = threadIdx.x;
    const int w   = tid >> 5;
    const int l   = tid & 31;
    const int ih  = l >> 4;                 // i-half: 0 -> i in [0,32), 1 -> [32,64)
    const int j   = (w << 4) + (l & 15);    // state column owned by this lane
    const float* fb = feats + (size_t)b * SS * TT;

    // ---- sequence length (mask is a prefix) ----
    const int mk = detect_mask_kind(mask);
    {
        int c = 0;
        const size_t base = (size_t)b * SS;
        for (int t = tid; t < SS; t += 128) c += mask_nz(mask, mk, base + t);
#pragma unroll
        for (int o = 16; o; o >>= 1) c += __shfl_down_sync(0xffffffffu, c, o);
        if ((tid & 31) == 0) swc[tid >> 5] = c;
        __syncthreads();
        if (tid == 0) sL = swc[0] + swc[1] + swc[2] + swc[3];
        __syncthreads();
    }
    const int L = sL;

    // ---- E packed as i-pairs: Epk[k] = (E[base+2k][j], E[base+2k+1][j]) ----
    unsigned long long Epk[16];
#pragma unroll
    for (int k = 0; k < 16; k++) {
        int i0 = (ih << 5) + 2 * k;
        unsigned e0 = __float_as_uint(__expf(trans[i0 * TT + j]));
        unsigned e1 = __float_as_uint(__expf(trans[(i0 + 1) * TT + j]));
        Epk[k] = ((unsigned long long)e1 << 32) | e0;
    }

    const bool store_lane = (l < 16);   // one writer per j

    // ---- init: w(0), scale(=1), feats prefetch ring ----
    if (store_lane) wbuf[0][j] = __expf(startt[j] + fb[j]);
    if (tid == 0) { sscale[0] = 1.0f; sscale[1] = 1.0f; }
    float rf0 = 0.f, rf1 = 0.f, rf2 = 0.f, rf3 = 0.f;
    if (store_lane) {
        rf0 = fb[(size_t)(1 < SS ? 1 : SS - 1) * TT + j];
        rf1 = fb[(size_t)(2 < SS ? 2 : SS - 1) * TT + j];
        rf2 = fb[(size_t)(3 < SS ? 3 : SS - 1) * TT + j];
        rf3 = fb[(size_t)(4 < SS ? 4 : SS - 1) * TT + j];
    }
    int LS = 0;       // cumulative applied exponent (meaningful on tid 0 only)
    int e_prev = 0;   // exponent computed last step (tid 0 only)
    __syncthreads();

    // ---- main recurrence: one barrier per step ----
    for (int t = 1; t < L; t++) {
        // Early loads (latency hidden under the matvec)
        float scale = sscale[(t + 1) & 1];     // written at step t-1 (lag-1)
        float g = 0.f;
        if (store_lane) g = __expf(rf0);

        // Half-matvec: 16 packed FMAs over this lane's 32 i's
        const ulonglong2* wv =
            reinterpret_cast<const ulonglong2*>(&wbuf[(t + 1) & 1][ih << 5]);
        unsigned long long a0 = 0ull, a1 = 0ull;   // f32x2 zeros
#pragma unroll
        for (int q = 0; q < 8; q++) {
            ulonglong2 v = wv[q];
            fma2(a0, v.x, Epk[2 * q]);
            fma2(a1, v.y, Epk[2 * q + 1]);
        }
        unsigned long long a = add2(a0, a1);
        unsigned lo, hi;
        asm("mov.b64 {%0,%1}, %2;" : "=r"(lo), "=r"(hi) : "l"(a));
        float s = __uint_as_float(lo) + __uint_as_float(hi);
        // combine the two i-halves: lanes l and l^16 hold the same j
        s += __shfl_xor_sync(0xffffffffu, s, 16);

        // scale-exponent tracker (s_0 lives on warp 0, lane 0)
        if (tid == 0) {
            LS += e_prev;
            e_prev = ((__float_as_int(s) >> 23) & 255) - 127;
            sscale[t & 1] = __int_as_float((127 - e_prev) << 23);
        }

        if (store_lane) {
            wbuf[t & 1][j] = s * scale * g;
            // rotate prefetch ring, issue next load (PF steps ahead)
            rf0 = rf1; rf1 = rf2; rf2 = rf3;
            int tp = t + PF; if (tp > SS - 1) tp = SS - 1;
            rf3 = fb[(size_t)tp * TT + j];
        }
        __syncthreads();
    }

    // ---- final logsumexp with end transitions (warp 0) ----
    if (w == 0) {
        const float* wf = wbuf[(L - 1) & 1];
        float v = wf[l] * __expf(endt[l]) + wf[l + 32] * __expf(endt[l + 32]);
#pragma unroll
        for (int o = 16; o; o >>= 1) v += __shfl_down_sync(0xffffffffu, v, o);
        if (l == 0)
            g_partial[b] = logf(v) + (float)LS * 0.693147180559945309f;
    }
}

// ---------------- gold (path score) kernel ----------------
__global__ void __launch_bounds__(256)
crf_gold_kernel(const float* __restrict__ feats,
                const float* __restrict__ trans,
                const float* __restrict__ startt,
                const float* __restrict__ endt,
                const void* __restrict__ tags,
                const void* __restrict__ mask) {
    __shared__ float swr[8];
    __shared__ int   swc[8];

    const int b   = blockIdx.x;
    const int tid = threadIdx.x;
    const int mk  = detect_mask_kind(mask);
    const bool t64 = detect_tags64(tags);
    const size_t base = (size_t)b * SS;

    float acc = 0.f;
    int   cnt = 0;
    for (int t = tid; t < SS; t += 256) {
        int m0 = mask_nz(mask, mk, base + t);
        cnt += m0;
        if (t < SS - 1) {
            int tg  = tag_at(tags, t64, base + t);
            int tg1 = tag_at(tags, t64, base + t + 1);
            int m1  = mask_nz(mask, mk, base + t + 1);
            float em = feats[(base + (size_t)t) * TT + tg];
            float tr = trans[tg * TT + tg1];
            acc += tr * (float)m1 + em * (float)m0;
        }
    }
#pragma unroll
    for (int o = 16; o; o >>= 1) {
        acc += __shfl_down_sync(0xffffffffu, acc, o);
        cnt += __shfl_down_sync(0xffffffffu, cnt, o);
    }
    if ((tid & 31) == 0) { swr[tid >> 5] = acc; swc[tid >> 5] = cnt; }
    __syncthreads();
    if (tid == 0) {
        float a = 0.f; int L = 0;
#pragma unroll
        for (int ww = 0; ww < 8; ww++) { a += swr[ww]; L += swc[ww]; }
        int first = tag_at(tags, t64, base);
        int last  = tag_at(tags, t64, base + L - 1);
        float gold = a + startt[first] + endt[last];
        if (mask_nz(mask, mk, base + SS - 1))
            gold += feats[(base + (size_t)(SS - 1)) * TT + last];
        g_partial[BB + b] = -gold;
    }
}

// ---------------- deterministic final reduction ----------------
__global__ void __launch_bounds__(256)
crf_reduce_kernel(float* __restrict__ out) {
    __shared__ float sred[8];
    int tid = threadIdx.x;
    float v = g_partial[tid] + g_partial[tid + BB];
#pragma unroll
    for (int o = 16; o; o >>= 1) v += __shfl_down_sync(0xffffffffu, v, o);
    if ((tid & 31) == 0) sred[tid >> 5] = v;
    __syncthreads();
    if (tid == 0) {
        float tot = 0.f;
#pragma unroll
        for (int ww = 0; ww < 8; ww++) tot += sred[ww];
        out[0] = tot;
    }
}

extern "C" void kernel_launch(void* const* d_in, const int* in_sizes, int n_in,
                              void* d_out, int out_size) {
    const float* feats  = (const float*)d_in[0];
    const float* trans  = (const float*)d_in[1];
    const float* startt = (const float*)d_in[2];
    const float* endt   = (const float*)d_in[3];
    const void*  tags   = d_in[4];
    const void*  mask   = d_in[5];
    float* out = (float*)d_out;

    crf_fwd_kernel<<<BB, 128>>>(feats, trans, startt, endt, mask);
    crf_gold_kernel<<<BB, 256>>>(feats, trans, startt, endt, tags, mask);
    crf_reduce_kernel<<<1, 256>>>(out);
}

// round 4
// speedup vs baseline: 2.1654x; 2.1654x over previous
#include <cuda_runtime.h>
#include <cstdint>

// Problem constants
#define BB 256
#define SS 2048
#define TT 64
#define TILE 16           // steps per feats tile (4 KB)
#define NBUF 4            // smem tile buffers
#define NTILES (SS / TILE)

// Partial results: [0..255] = fwd per batch, [256..511] = -gold per batch
__device__ float g_partial[2 * BB];

// ---------------- dtype detection helpers ----------------
// mask: 0 = uint8 (bool), 1 = int32, 2 = float32
__device__ __forceinline__ int detect_mask_kind(const void* m) {
    unsigned u = *reinterpret_cast<const unsigned*>(m);
    if (u == 0x3f800000u) return 2;      // float 1.0
    if (u == 1u)          return 1;      // int32 1
    return 0;                             // bytes 01 01 01 01 (bool; L>=1024 so first 4 true)
}
__device__ __forceinline__ int mask_nz(const void* m, int kind, size_t i) {
    if (kind == 0) return reinterpret_cast<const unsigned char*>(m)[i] != 0;
    if (kind == 1) return reinterpret_cast<const int*>(m)[i] != 0;
    return reinterpret_cast<const float*>(m)[i] != 0.0f;
}
__device__ __forceinline__ bool detect_tags64(const void* t) {
    const int* p = reinterpret_cast<const int*>(t);
    bool all_hi_zero = true;
#pragma unroll
    for (int k = 0; k < 8; k++)
        if (p[2 * k + 1] != 0) all_hi_zero = false;
    return all_hi_zero;
}
__device__ __forceinline__ int tag_at(const void* t, bool is64, size_t i) {
    if (is64) return (int)reinterpret_cast<const long long*>(t)[i];
    return reinterpret_cast<const int*>(t)[i];
}

// ---------------- packed f32x2 helpers ----------------
__device__ __forceinline__ void fma2(unsigned long long& d,
                                     unsigned long long a, unsigned long long b) {
    asm("fma.rn.f32x2 %0, %1, %2, %0;" : "+l"(d) : "l"(a), "l"(b));
}
__device__ __forceinline__ unsigned long long add2(unsigned long long a,
                                                   unsigned long long b) {
    unsigned long long d;
    asm("add.rn.f32x2 %0, %1, %2;" : "=l"(d) : "l"(a), "l"(b));
    return d;
}

// ---------------- forward (log-partition) kernel ----------------
// One CTA (4 warps) per batch chain. Warp w owns states j in [16w, 16w+16);
// lanes l and l^16 duplicate j, splitting the i-sum into halves of 32.
// Linear-domain recurrence with lag-1 power-of-2 rescale (exact), one
// __syncthreads per step. feats staged in SMEM via cp.async, 2 tiles ahead,
// so NO global-memory latency sits on the recurrence's critical path.
__global__ void __launch_bounds__(128)
crf_fwd_kernel(const float* __restrict__ feats,
               const float* __restrict__ trans,
               const float* __restrict__ startt,
               const float* __restrict__ endt,
               const void* __restrict__ mask) {
    __shared__ __align__(16) float sf[NBUF][TILE * TT];   // feats tiles (16 KB)
    __shared__ __align__(16) float wbuf[2][TT];
    __shared__ float sscale[2];
    __shared__ int   swc[4];
    __shared__ int   sL;

    const int b   = blockIdx.x;
    const int tid = threadIdx.x;
    const int w   = tid >> 5;
    const int l   = tid & 31;
    const int ih  = l >> 4;                 // i-half: 0 -> i in [0,32), 1 -> [32,64)
    const int j   = (w << 4) + (l & 15);    // state column owned by this lane
    const float* fb = feats + (size_t)b * SS * TT;

    // ---- tile loader: tile k = steps [k*TILE, k*TILE+TILE) (4 KB contiguous) ----
    auto issue_tile = [&](int k) {
        if (k < NTILES) {
            const float* src = fb + (size_t)k * TILE * TT + tid * 4;
            unsigned dst = (unsigned)__cvta_generic_to_shared(&sf[k & (NBUF - 1)][tid * 4]);
            asm volatile("cp.async.ca.shared.global [%0], [%1], 16;" :: "r"(dst), "l"(src));
            asm volatile("cp.async.ca.shared.global [%0], [%1], 16;"
                         :: "r"(dst + 2048), "l"(src + 512));
        }
        asm volatile("cp.async.commit_group;");
    };

    // ---- kick off tiles 0..2 immediately (DRAM latency hides under setup) ----
    issue_tile(0);
    issue_tile(1);
    issue_tile(2);

    // ---- sequence length (mask is a prefix) ----
    const int mk = detect_mask_kind(mask);
    {
        int c = 0;
        const size_t base = (size_t)b * SS;
        for (int t = tid; t < SS; t += 128) c += mask_nz(mask, mk, base + t);
#pragma unroll
        for (int o = 16; o; o >>= 1) c += __shfl_down_sync(0xffffffffu, c, o);
        if ((tid & 31) == 0) swc[tid >> 5] = c;
        __syncthreads();
        if (tid == 0) sL = swc[0] + swc[1] + swc[2] + swc[3];
    }

    // ---- E packed as i-pairs: Epk[k] = (E[base+2k][j], E[base+2k+1][j]) ----
    unsigned long long Epk[16];
#pragma unroll
    for (int k = 0; k < 16; k++) {
        int i0 = (ih << 5) + 2 * k;
        unsigned e0 = __float_as_uint(__expf(trans[i0 * TT + j]));
        unsigned e1 = __float_as_uint(__expf(trans[(i0 + 1) * TT + j]));
        Epk[k] = ((unsigned long long)e1 << 32) | e0;
    }

    const bool store_lane = (l < 16);   // one writer per j

    // ---- init: w(0), scale(=1) ----
    if (store_lane) wbuf[0][j] = __expf(startt[j] + fb[j]);
    if (tid == 0) { sscale[0] = 1.0f; sscale[1] = 1.0f; }
    int LS = 0;       // cumulative applied exponent (meaningful on tid 0 only)
    int e_prev = 0;   // exponent computed last step (tid 0 only)

    // tile 0 must be resident before step 1 reads it
    asm volatile("cp.async.wait_group 2;" ::: "memory");
    __syncthreads();
    const int L = sL;

    // ---- main recurrence: one barrier per step, tile refill every 16 steps ----
    for (int t = 1; t < L; t++) {
        if ((t & (TILE - 1)) == 0) {
            // entering tile k = t/TILE: refill buffer (k+2)%NBUF (consumed as
            // tile k-2), then ensure tile k is resident (leave newest 2 pending).
            int k = t >> 4;
            issue_tile(k + 2);
            asm volatile("cp.async.wait_group 2;" ::: "memory");
            __syncthreads();
        }

        float scale = sscale[(t + 1) & 1];     // written at step t-1 (lag-1)
        float g = 0.f;
        if (store_lane)
            g = __expf(sf[(t >> 4) & (NBUF - 1)][((t & (TILE - 1)) << 6) + j]);

        // Half-matvec: 16 packed FMAs over this lane's 32 i's
        const ulonglong2* wv =
            reinterpret_cast<const ulonglong2*>(&wbuf[(t + 1) & 1][ih << 5]);
        unsigned long long a0 = 0ull, a1 = 0ull;   // f32x2 zeros
#pragma unroll
        for (int q = 0; q < 8; q++) {
            ulonglong2 v = wv[q];
            fma2(a0, v.x, Epk[2 * q]);
            fma2(a1, v.y, Epk[2 * q + 1]);
        }
        unsigned long long a = add2(a0, a1);
        unsigned lo, hi;
        asm("mov.b64 {%0,%1}, %2;" : "=r"(lo), "=r"(hi) : "l"(a));
        float s = __uint_as_float(lo) + __uint_as_float(hi);
        // combine the two i-halves: lanes l and l^16 hold the same j
        s += __shfl_xor_sync(0xffffffffu, s, 16);

        // scale-exponent tracker (s_0 lives on warp 0, lane 0)
        if (tid == 0) {
            LS += e_prev;
            e_prev = ((__float_as_int(s) >> 23) & 255) - 127;
            sscale[t & 1] = __int_as_float((127 - e_prev) << 23);
        }

        if (store_lane) wbuf[t & 1][j] = s * scale * g;
        __syncthreads();
    }

    // ---- final logsumexp with end transitions (warp 0) ----
    if (w == 0) {
        const float* wf = wbuf[(L - 1) & 1];
        float v = wf[l] * __expf(endt[l]) + wf[l + 32] * __expf(endt[l + 32]);
#pragma unroll
        for (int o = 16; o; o >>= 1) v += __shfl_down_sync(0xffffffffu, v, o);
        if (l == 0)
            g_partial[b] = logf(v) + (float)LS * 0.693147180559945309f;
    }
    // drain outstanding async copies before exit
    asm volatile("cp.async.wait_group 0;" ::: "memory");
}

// ---------------- gold (path score) kernel ----------------
__global__ void __launch_bounds__(256)
crf_gold_kernel(const float* __restrict__ feats,
                const float* __restrict__ trans,
                const float* __restrict__ startt,
                const float* __restrict__ endt,
                const void* __restrict__ tags,
                const void* __restrict__ mask) {
    __shared__ float swr[8];
    __shared__ int   swc[8];

    const int b   = blockIdx.x;
    const int tid = threadIdx.x;
    const int mk  = detect_mask_kind(mask);
    const bool t64 = detect_tags64(tags);
    const size_t base = (size_t)b * SS;

    float acc = 0.f;
    int   cnt = 0;
    for (int t = tid; t < SS; t += 256) {
        int m0 = mask_nz(mask, mk, base + t);
        cnt += m0;
        if (t < SS - 1) {
            int tg  = tag_at(tags, t64, base + t);
            int tg1 = tag_at(tags, t64, base + t + 1);
            int m1  = mask_nz(mask, mk, base + t + 1);
            float em = feats[(base + (size_t)t) * TT + tg];
            float tr = trans[tg * TT + tg1];
            acc += tr * (float)m1 + em * (float)m0;
        }
    }
#pragma unroll
    for (int o = 16; o; o >>= 1) {
        acc += __shfl_down_sync(0xffffffffu, acc, o);
        cnt += __shfl_down_sync(0xffffffffu, cnt, o);
    }
    if ((tid & 31) == 0) { swr[tid >> 5] = acc; swc[tid >> 5] = cnt; }
    __syncthreads();
    if (tid == 0) {
        float a = 0.f; int L = 0;
#pragma unroll
        for (int ww = 0; ww < 8; ww++) { a += swr[ww]; L += swc[ww]; }
        int first = tag_at(tags, t64, base);
        int last  = tag_at(tags, t64, base + L - 1);
        float gold = a + startt[first] + endt[last];
        if (mask_nz(mask, mk, base + SS - 1))
            gold += feats[(base + (size_t)(SS - 1)) * TT + last];
        g_partial[BB + b] = -gold;
    }
}

// ---------------- deterministic final reduction ----------------
__global__ void __launch_bounds__(256)
crf_reduce_kernel(float* __restrict__ out) {
    __shared__ float sred[8];
    int tid = threadIdx.x;
    float v = g_partial[tid] + g_partial[tid + BB];
#pragma unroll
    for (int o = 16; o; o >>= 1) v += __shfl_down_sync(0xffffffffu, v, o);
    if ((tid & 31) == 0) sred[tid >> 5] = v;
    __syncthreads();
    if (tid == 0) {
        float tot = 0.f;
#pragma unroll
        for (int ww = 0; ww < 8; ww++) tot += sred[ww];
        out[0] = tot;
    }
}

extern "C" void kernel_launch(void* const* d_in, const int* in_sizes, int n_in,
                              void* d_out, int out_size) {
    const float* feats  = (const float*)d_in[0];
    const float* trans  = (const float*)d_in[1];
    const float* startt = (const float*)d_in[2];
    const float* endt   = (const float*)d_in[3];
    const void*  tags   = d_in[4];
    const void*  mask   = d_in[5];
    float* out = (float*)d_out;

    crf_fwd_kernel<<<BB, 128>>>(feats, trans, startt, endt, mask);
    crf_gold_kernel<<<BB, 256>>>(feats, trans, startt, endt, tags, mask);
    crf_reduce_kernel<<<1, 256>>>(out);
}

// round 5
// speedup vs baseline: 3.4323x; 1.5851x over previous
#include <cuda_runtime.h>
#include <cstdint>

// Problem constants
#define BB 256
#define SS 2048
#define TT 64
#define CH 4                  // chains (warps) per CTA
#define NCTA (BB / CH)        // 64 CTAs
#define TILE 8                // steps per feats tile (2 KB per chain)
#define NBUF 4
#define NTILES (SS / TILE)    // 256

// Partial results: [0..255] = fwd per batch, [256..511] = -gold per batch
__device__ float g_partial[2 * BB];

// ---------------- dtype detection helpers ----------------
__device__ __forceinline__ int detect_mask_kind(const void* m) {
    unsigned u = *reinterpret_cast<const unsigned*>(m);
    if (u == 0x3f800000u) return 2;      // float 1.0
    if (u == 1u)          return 1;      // int32 1
    return 0;                             // packed bool bytes
}
__device__ __forceinline__ int mask_nz(const void* m, int kind, size_t i) {
    if (kind == 0) return reinterpret_cast<const unsigned char*>(m)[i] != 0;
    if (kind == 1) return reinterpret_cast<const int*>(m)[i] != 0;
    return reinterpret_cast<const float*>(m)[i] != 0.0f;
}
__device__ __forceinline__ bool detect_tags64(const void* t) {
    const int* p = reinterpret_cast<const int*>(t);
    bool all_hi_zero = true;
#pragma unroll
    for (int k = 0; k < 8; k++)
        if (p[2 * k + 1] != 0) all_hi_zero = false;
    return all_hi_zero;
}
__device__ __forceinline__ int tag_at(const void* t, bool is64, size_t i) {
    if (is64) return (int)reinterpret_cast<const long long*>(t)[i];
    return reinterpret_cast<const int*>(t)[i];
}

// ---------------- packed f32x2 helpers ----------------
__device__ __forceinline__ void fma2(unsigned long long& d,
                                     unsigned long long a, unsigned long long b) {
    asm("fma.rn.f32x2 %0, %1, %2, %0;" : "+l"(d) : "l"(a), "l"(b));
}
__device__ __forceinline__ unsigned long long add2(unsigned long long a,
                                                   unsigned long long b) {
    unsigned long long d;
    asm("add.rn.f32x2 %0, %1, %2;" : "=l"(d) : "l"(a), "l"(b));
    return d;
}
__device__ __forceinline__ unsigned long long pk2(float x, float y) {
    unsigned long long d;
    asm("mov.b64 %0, {%1, %2};" : "=l"(d) : "r"(__float_as_uint(x)), "r"(__float_as_uint(y)));
    return d;
}
__device__ __forceinline__ float hadd2(unsigned long long a) {
    unsigned lo, hi;
    asm("mov.b64 {%0,%1}, %2;" : "=r"(lo), "=r"(hi) : "l"(a));
    return __uint_as_float(lo) + __uint_as_float(hi);
}

// ---------------- forward (log-partition) kernel ----------------
// ONE WARP per chain; 4 independent chains per CTA (one per SMSP).
// Lane l owns states j0=2l, j1=2l+1; the whole E=exp(trans) matrix is in
// registers (packed f32x2 over i-pairs). Per step: 16 broadcast LDS.128 of w,
// 64 packed FMAs, lane-local rescale — no cross-lane combine, no
// __syncthreads, one __syncwarp. feats staged via per-warp cp.async pipeline.
__global__ void __launch_bounds__(128, 1)
crf_fwd_kernel(const float* __restrict__ feats,
               const float* __restrict__ trans,
               const float* __restrict__ startt,
               const float* __restrict__ endt,
               const void* __restrict__ mask) {
    __shared__ __align__(16) float sf[CH][NBUF][TILE * TT];   // 32 KB
    __shared__ __align__(16) float wbuf[CH][2][TT];           // 2 KB

    const int tid = threadIdx.x;
    const int ch  = tid >> 5;
    const int l   = tid & 31;
    const int b   = blockIdx.x * CH + ch;
    const int j0  = 2 * l;
    const float* fb = feats + (size_t)b * SS * TT;

    // per-lane cp.async tile loader: tile k covers steps [k*TILE, k*TILE+TILE)
    auto issue_tile = [&](int k) {
        if (k < NTILES) {
            const char* src = reinterpret_cast<const char*>(fb) + (size_t)k * TILE * TT * 4 + l * 64;
            unsigned dst = (unsigned)__cvta_generic_to_shared(
                reinterpret_cast<char*>(&sf[ch][k & (NBUF - 1)][0]) + l * 64);
#pragma unroll
            for (int c = 0; c < 4; c++)
                asm volatile("cp.async.ca.shared.global [%0], [%1], 16;"
                             :: "r"(dst + c * 16), "l"(src + c * 16));
        }
        asm volatile("cp.async.commit_group;");
    };

    issue_tile(0);
    issue_tile(1);
    issue_tile(2);

    // ---- sequence length (mask is a prefix), warp-local, all lanes get L ----
    const int mk = detect_mask_kind(mask);
    int L;
    {
        int c = 0;
        const size_t base = (size_t)b * SS;
        for (int t = l; t < SS; t += 32) c += mask_nz(mask, mk, base + t);
#pragma unroll
        for (int o = 16; o; o >>= 1) c += __shfl_xor_sync(0xffffffffu, c, o);
        L = c;
    }

    // ---- E in registers: E0[k]=(E[2k][j0],E[2k+1][j0]), E1 for j1 ----
    unsigned long long E0[32], E1[32];
#pragma unroll
    for (int k = 0; k < 32; k++) {
        float2 ra = *reinterpret_cast<const float2*>(trans + (2 * k) * TT + j0);
        float2 rb = *reinterpret_cast<const float2*>(trans + (2 * k + 1) * TT + j0);
        E0[k] = pk2(__expf(ra.x), __expf(rb.x));
        E1[k] = pk2(__expf(ra.y), __expf(rb.y));
    }

    // ---- init w(0) ----
    {
        float2 f0 = *reinterpret_cast<const float2*>(fb + j0);
        float2 st = *reinterpret_cast<const float2*>(startt + j0);
        *reinterpret_cast<float2*>(&wbuf[ch][0][j0]) =
            make_float2(__expf(st.x + f0.x), __expf(st.y + f0.y));
    }
    float scale = 1.0f;
    int e_cur = 0, LS = 0;

    asm volatile("cp.async.wait_group 2;" ::: "memory");
    __syncwarp();

    // ---- main recurrence: warp-private, one __syncwarp per step ----
    for (int t = 1; t < L; t++) {
        if ((t & (TILE - 1)) == 0) {
            int k = t >> 3;
            issue_tile(k + 2);
            asm volatile("cp.async.wait_group 2;" ::: "memory");
            __syncwarp();
        }

        // emission factors (early; MUFU latency hides under the matvec)
        float2 fg = *reinterpret_cast<const float2*>(
            &sf[ch][(t >> 3) & (NBUF - 1)][((t & (TILE - 1)) << 6) + j0]);
        float g0 = __expf(fg.x), g1 = __expf(fg.y);

        // matvec rows j0, j1: 64 packed FMAs over broadcast w
        const ulonglong2* wv =
            reinterpret_cast<const ulonglong2*>(wbuf[ch][(t + 1) & 1]);
        unsigned long long a0 = 0ull, a1 = 0ull, b0 = 0ull, b1 = 0ull;
#pragma unroll
        for (int q = 0; q < 16; q++) {
            ulonglong2 v = wv[q];
            fma2(a0, v.x, E0[2 * q]);
            fma2(a1, v.y, E0[2 * q + 1]);
            fma2(b0, v.x, E1[2 * q]);
            fma2(b1, v.y, E1[2 * q + 1]);
        }
        float s0 = hadd2(add2(a0, a1));
        float s1 = hadd2(add2(b0, b1));

        // apply lag-1 power-of-2 rescale (exact), then derive next scale from
        // state 0 (lane 0's s0) — shfl latency is off the critical path.
        LS += e_cur;
        float wn0 = s0 * scale * g0;
        float wn1 = s1 * scale * g1;
        *reinterpret_cast<float2*>(&wbuf[ch][t & 1][j0]) = make_float2(wn0, wn1);

        float s0b = __shfl_sync(0xffffffffu, s0, 0);
        e_cur = ((__float_as_int(s0b) >> 23) & 255) - 127;
        scale = __int_as_float((127 - e_cur) << 23);

        __syncwarp();
    }

    // ---- final logsumexp with end transitions (warp-local) ----
    {
        const float* wf = wbuf[ch][(L - 1) & 1];
        float2 wp = *reinterpret_cast<const float2*>(&wf[j0]);
        float2 ep = *reinterpret_cast<const float2*>(endt + j0);
        float v = wp.x * __expf(ep.x) + wp.y * __expf(ep.y);
#pragma unroll
        for (int o = 16; o; o >>= 1) v += __shfl_down_sync(0xffffffffu, v, o);
        if (l == 0)
            g_partial[b] = logf(v) + (float)LS * 0.693147180559945309f;
    }
    asm volatile("cp.async.wait_group 0;" ::: "memory");
}

// ---------------- gold (path score) kernel ----------------
__global__ void __launch_bounds__(256)
crf_gold_kernel(const float* __restrict__ feats,
                const float* __restrict__ trans,
                const float* __restrict__ startt,
                const float* __restrict__ endt,
                const void* __restrict__ tags,
                const void* __restrict__ mask) {
    __shared__ float swr[8];
    __shared__ int   swc[8];

    const int b   = blockIdx.x;
    const int tid = threadIdx.x;
    const int mk  = detect_mask_kind(mask);
    const bool t64 = detect_tags64(tags);
    const size_t base = (size_t)b * SS;

    float acc = 0.f;
    int   cnt = 0;
    for (int t = tid; t < SS; t += 256) {
        int m0 = mask_nz(mask, mk, base + t);
        cnt += m0;
        if (t < SS - 1) {
            int tg  = tag_at(tags, t64, base + t);
            int tg1 = tag_at(tags, t64, base + t + 1);
            int m1  = mask_nz(mask, mk, base + t + 1);
            float em = feats[(base + (size_t)t) * TT + tg];
            float tr = trans[tg * TT + tg1];
            acc += tr * (float)m1 + em * (float)m0;
        }
    }
#pragma unroll
    for (int o = 16; o; o >>= 1) {
        acc += __shfl_down_sync(0xffffffffu, acc, o);
        cnt += __shfl_down_sync(0xffffffffu, cnt, o);
    }
    if ((tid & 31) == 0) { swr[tid >> 5] = acc; swc[tid >> 5] = cnt; }
    __syncthreads();
    if (tid == 0) {
        float a = 0.f; int L = 0;
#pragma unroll
        for (int ww = 0; ww < 8; ww++) { a += swr[ww]; L += swc[ww]; }
        int first = tag_at(tags, t64, base);
        int last  = tag_at(tags, t64, base + L - 1);
        float gold = a + startt[first] + endt[last];
        if (mask_nz(mask, mk, base + SS - 1))
            gold += feats[(base + (size_t)(SS - 1)) * TT + last];
        g_partial[BB + b] = -gold;
    }
}

// ---------------- deterministic final reduction ----------------
__global__ void __launch_bounds__(256)
crf_reduce_kernel(float* __restrict__ out) {
    __shared__ float sred[8];
    int tid = threadIdx.x;
    float v = g_partial[tid] + g_partial[tid + BB];
#pragma unroll
    for (int o = 16; o; o >>= 1) v += __shfl_down_sync(0xffffffffu, v, o);
    if ((tid & 31) == 0) sred[tid >> 5] = v;
    __syncthreads();
    if (tid == 0) {
        float tot = 0.f;
#pragma unroll
        for (int ww = 0; ww < 8; ww++) tot += sred[ww];
        out[0] = tot;
    }
}

extern "C" void kernel_launch(void* const* d_in, const int* in_sizes, int n_in,
                              void* d_out, int out_size) {
    const float* feats  = (const float*)d_in[0];
    const float* trans  = (const float*)d_in[1];
    const float* startt = (const float*)d_in[2];
    const float* endt   = (const float*)d_in[3];
    const void*  tags   = d_in[4];
    const void*  mask   = d_in[5];
    float* out = (float*)d_out;

    crf_fwd_kernel<<<NCTA, 128>>>(feats, trans, startt, endt, mask);
    crf_gold_kernel<<<BB, 256>>>(feats, trans, startt, endt, tags, mask);
    crf_reduce_kernel<<<1, 256>>>(out);
}

// round 6
// speedup vs baseline: 4.5422x; 1.3234x over previous
#include <cuda_runtime.h>
#include <cstdint>

// Problem constants
#define BB 256
#define SS 2048
#define TT 64
#define CH 2                  // chains per CTA (2 warps per chain)
#define NCTA (BB / CH)        // 128 CTAs
#define TILE 8                // steps per feats tile (2 KB per chain)
#define NBUF 4
#define NTILES (SS / TILE)    // 256

// Partial results: [0..255] = fwd per batch, [256..511] = -gold per batch
__device__ float g_partial[2 * BB];

// ---------------- dtype detection helpers ----------------
__device__ __forceinline__ int detect_mask_kind(const void* m) {
    unsigned u = *reinterpret_cast<const unsigned*>(m);
    if (u == 0x3f800000u) return 2;      // float 1.0
    if (u == 1u)          return 1;      // int32 1
    return 0;                             // packed bool bytes
}
__device__ __forceinline__ int mask_nz(const void* m, int kind, size_t i) {
    if (kind == 0) return reinterpret_cast<const unsigned char*>(m)[i] != 0;
    if (kind == 1) return reinterpret_cast<const int*>(m)[i] != 0;
    return reinterpret_cast<const float*>(m)[i] != 0.0f;
}
__device__ __forceinline__ bool detect_tags64(const void* t) {
    const int* p = reinterpret_cast<const int*>(t);
    bool all_hi_zero = true;
#pragma unroll
    for (int k = 0; k < 8; k++)
        if (p[2 * k + 1] != 0) all_hi_zero = false;
    return all_hi_zero;
}
__device__ __forceinline__ int tag_at(const void* t, bool is64, size_t i) {
    if (is64) return (int)reinterpret_cast<const long long*>(t)[i];
    return reinterpret_cast<const int*>(t)[i];
}

// ---------------- packed f32x2 helpers ----------------
__device__ __forceinline__ void fma2(unsigned long long& d,
                                     unsigned long long a, unsigned long long b) {
    asm("fma.rn.f32x2 %0, %1, %2, %0;" : "+l"(d) : "l"(a), "l"(b));
}
__device__ __forceinline__ unsigned long long add2(unsigned long long a,
                                                   unsigned long long b) {
    unsigned long long d;
    asm("add.rn.f32x2 %0, %1, %2;" : "=l"(d) : "l"(a), "l"(b));
    return d;
}
__device__ __forceinline__ unsigned long long pk2(float x, float y) {
    unsigned long long d;
    asm("mov.b64 %0, {%1, %2};" : "=l"(d) : "r"(__float_as_uint(x)), "r"(__float_as_uint(y)));
    return d;
}
__device__ __forceinline__ float hadd2(unsigned long long a) {
    unsigned lo, hi;
    asm("mov.b64 {%0,%1}, %2;" : "=r"(lo), "=r"(hi) : "l"(a));
    return __uint_as_float(lo) + __uint_as_float(hi);
}

// ---------------- forward (log-partition) kernel ----------------
// TWO WARPS per chain, 2 chains per CTA (4 warps -> 4 SMSPs, 128 CTAs ~= 1/SM).
// Warp sw of a chain owns states j in [32sw, 32sw+32); lane owns ONE state j
// and sums over all 64 i with 32 packed FMA2 (halves the per-SMSP FMA issue
// floor vs whole-chain-per-warp). Chain-private NAMED barrier (64 threads) is
// the only cross-warp sync: one per step. Linear-domain recurrence with lag-1
// power-of-2 rescale posted through double-buffered smem by warp0-lane0
// (state 0) — no shfl on the critical path. feats staged via cp.async tiles.
__global__ void __launch_bounds__(128)
crf_fwd_kernel(const float* __restrict__ feats,
               const float* __restrict__ trans,
               const float* __restrict__ startt,
               const float* __restrict__ endt,
               const void* __restrict__ mask) {
    __shared__ __align__(16) float sf[CH][NBUF][TILE * TT];   // 16 KB
    __shared__ __align__(16) float wbuf[CH][2][TT];           // 1 KB
    __shared__ float sscale[CH][2];
    __shared__ float sred[CH][2];

    const int tid  = threadIdx.x;
    const int wid  = tid >> 5;
    const int l    = tid & 31;
    const int ch   = wid >> 1;         // chain within CTA
    const int sw   = wid & 1;          // sub-warp within chain
    const int wtid = (sw << 5) + l;    // 0..63 within chain
    const int b    = blockIdx.x * CH + ch;
    const int j    = (sw << 5) + l;    // this lane's state
    const int barid = 1 + ch;          // named barrier per chain
    const float* fb = feats + (size_t)b * SS * TT;

    // chain-wide named barrier (64 threads)
    auto chain_bar = [&]() {
        asm volatile("bar.sync %0, 64;" :: "r"(barid) : "memory");
    };

    // per-chain cp.async tile loader: tile k covers steps [k*TILE, k*TILE+TILE)
    auto issue_tile = [&](int k) {
        if (k < NTILES) {
            const char* src = reinterpret_cast<const char*>(fb)
                              + (size_t)k * TILE * TT * 4 + wtid * 32;
            unsigned dst = (unsigned)__cvta_generic_to_shared(
                reinterpret_cast<char*>(&sf[ch][k & (NBUF - 1)][0]) + wtid * 32);
            asm volatile("cp.async.ca.shared.global [%0], [%1], 16;"
                         :: "r"(dst), "l"(src));
            asm volatile("cp.async.ca.shared.global [%0], [%1], 16;"
                         :: "r"(dst + 16), "l"(src + 16));
        }
        asm volatile("cp.async.commit_group;");
    };

    issue_tile(0);
    issue_tile(1);
    issue_tile(2);

    // ---- sequence length (mask is a prefix), warp-local ----
    const int mk = detect_mask_kind(mask);
    int L;
    {
        int c = 0;
        const size_t base = (size_t)b * SS;
        for (int t = l; t < SS; t += 32) c += mask_nz(mask, mk, base + t);
#pragma unroll
        for (int o = 16; o; o >>= 1) c += __shfl_xor_sync(0xffffffffu, c, o);
        L = c;
    }

    // ---- E column j in registers, packed over i-pairs:
    //      E[k] = (exp(trans[2k][j]), exp(trans[2k+1][j])) ----
    unsigned long long E[32];
#pragma unroll
    for (int k = 0; k < 32; k++) {
        float ea = trans[(2 * k) * TT + j];
        float eb = trans[(2 * k + 1) * TT + j];
        E[k] = pk2(__expf(ea), __expf(eb));
    }

    // ---- init w(0), sscale ----
    wbuf[ch][0][j] = __expf(startt[j] + fb[j]);
    if (wtid == 0) { sscale[ch][0] = 1.0f; sscale[ch][1] = 1.0f; }
    int e_cur = 0, LS = 0;     // meaningful on warp0-lane0 (state 0) only

    asm volatile("cp.async.wait_group 2;" ::: "memory");
    chain_bar();

    // ---- main recurrence: one named barrier per step ----
    for (int t = 1; t < L; t++) {
        if ((t & (TILE - 1)) == 0) {
            int k = t >> 3;
            issue_tile(k + 2);
            asm volatile("cp.async.wait_group 2;" ::: "memory");
            chain_bar();
        }

        // lag-1 scale (posted at step t-1) + emission factor (early loads)
        float scale = sscale[ch][(t + 1) & 1];
        float fg = sf[ch][(t >> 3) & (NBUF - 1)][((t & (TILE - 1)) << 6) + j];
        float g = exp2f(fg * 1.44269504f);

        // row j of the matvec: 32 packed FMA2 over broadcast w (16 LDS.128)
        const ulonglong2* wv =
            reinterpret_cast<const ulonglong2*>(wbuf[ch][(t + 1) & 1]);
        unsigned long long a0 = 0ull, a1 = 0ull, a2 = 0ull, a3 = 0ull;
#pragma unroll
        for (int q = 0; q < 8; q++) {
            ulonglong2 v1 = wv[2 * q];
            ulonglong2 v2 = wv[2 * q + 1];
            fma2(a0, v1.x, E[4 * q + 0]);
            fma2(a1, v1.y, E[4 * q + 1]);
            fma2(a2, v2.x, E[4 * q + 2]);
            fma2(a3, v2.y, E[4 * q + 3]);
        }
        float s = hadd2(add2(add2(a0, a1), add2(a2, a3)));

        wbuf[ch][t & 1][j] = s * (g * scale);

        // scale-exponent tracker: state 0 lives on warp0-lane0; lag-1 post
        if (wtid == 0) {
            LS += e_cur;
            e_cur = ((__float_as_int(s) >> 23) & 255) - 127;
            sscale[ch][t & 1] = __int_as_float((127 - e_cur) << 23);
        }
        chain_bar();
    }

    // ---- final logsumexp with end transitions ----
    {
        float v = wbuf[ch][(L - 1) & 1][j] * __expf(endt[j]);
#pragma unroll
        for (int o = 16; o; o >>= 1) v += __shfl_down_sync(0xffffffffu, v, o);
        if (l == 0) sred[ch][sw] = v;
        chain_bar();
        if (wtid == 0)
            g_partial[b] = logf(sred[ch][0] + sred[ch][1])
                         + (float)LS * 0.693147180559945309f;
    }
    asm volatile("cp.async.wait_group 0;" ::: "memory");
}

// ---------------- gold (path score) kernel ----------------
__global__ void __launch_bounds__(256)
crf_gold_kernel(const float* __restrict__ feats,
                const float* __restrict__ trans,
                const float* __restrict__ startt,
                const float* __restrict__ endt,
                const void* __restrict__ tags,
                const void* __restrict__ mask) {
    __shared__ float swr[8];
    __shared__ int   swc[8];

    const int b   = blockIdx.x;
    const int tid = threadIdx.x;
    const int mk  = detect_mask_kind(mask);
    const bool t64 = detect_tags64(tags);
    const size_t base = (size_t)b * SS;

    float acc = 0.f;
    int   cnt = 0;
    for (int t = tid; t < SS; t += 256) {
        int m0 = mask_nz(mask, mk, base + t);
        cnt += m0;
        if (t < SS - 1) {
            int tg  = tag_at(tags, t64, base + t);
            int tg1 = tag_at(tags, t64, base + t + 1);
            int m1  = mask_nz(mask, mk, base + t + 1);
            float em = feats[(base + (size_t)t) * TT + tg];
            float tr = trans[tg * TT + tg1];
            acc += tr * (float)m1 + em * (float)m0;
        }
    }
#pragma unroll
    for (int o = 16; o; o >>= 1) {
        acc += __shfl_down_sync(0xffffffffu, acc, o);
        cnt += __shfl_down_sync(0xffffffffu, cnt, o);
    }
    if ((tid & 31) == 0) { swr[tid >> 5] = acc; swc[tid >> 5] = cnt; }
    __syncthreads();
    if (tid == 0) {
        float a = 0.f; int L = 0;
#pragma unroll
        for (int ww = 0; ww < 8; ww++) { a += swr[ww]; L += swc[ww]; }
        int first = tag_at(tags, t64, base);
        int last  = tag_at(tags, t64, base + L - 1);
        float gold = a + startt[first] + endt[last];
        if (mask_nz(mask, mk, base + SS - 1))
            gold += feats[(base + (size_t)(SS - 1)) * TT + last];
        g_partial[BB + b] = -gold;
    }
}

// ---------------- deterministic final reduction ----------------
__global__ void __launch_bounds__(256)
crf_reduce_kernel(float* __restrict__ out) {
    __shared__ float sred[8];
    int tid = threadIdx.x;
    float v = g_partial[tid] + g_partial[tid + BB];
#pragma unroll
    for (int o = 16; o; o >>= 1) v += __shfl_down_sync(0xffffffffu, v, o);
    if ((tid & 31) == 0) sred[tid >> 5] = v;
    __syncthreads();
    if (tid == 0) {
        float tot = 0.f;
#pragma unroll
        for (int ww = 0; ww < 8; ww++) tot += sred[ww];
        out[0] = tot;
    }
}

extern "C" void kernel_launch(void* const* d_in, const int* in_sizes, int n_in,
                              void* d_out, int out_size) {
    const float* feats  = (const float*)d_in[0];
    const float* trans  = (const float*)d_in[1];
    const float* startt = (const float*)d_in[2];
    const float* endt   = (const float*)d_in[3];
    const void*  tags   = d_in[4];
    const void*  mask   = d_in[5];
    float* out = (float*)d_out;

    crf_fwd_kernel<<<NCTA, 128>>>(feats, trans, startt, endt, mask);
    crf_gold_kernel<<<BB, 256>>>(feats, trans, startt, endt, tags, mask);
    crf_reduce_kernel<<<1, 256>>>(out);
}